// round 16
// baseline (speedup 1.0000x reference)
#include <cuda_runtime.h>
#include <cuda_bf16.h>
#include <cstdint>

// GruDirection3d forward wavefront:
//   out[d,y,x] = z*h_tilde + (1-z)*out[d-1,y-1,x-1],  border -> h0
//
// R16: un-sinkable prefetch. Evidence R1..R15: every register-prefetch
// variant pins at ~750 cyc/plane = critical path + ONE exposed DRAM trip,
// i.e. ptxas sinks the prefetch LDGs to their use point. Fix: z/h_tilde
// stream through a 5-slot cp.async.cg smem ring (issues at program point,
// wait_group(4) -> genuine depth-4 pipeline, zero register cost). z/h are
// element-wise so each thread fills and consumes ITS OWN ring element: no
// barrier for the ring. Prev-plane exchange = R13's linear float4 staging
// (LDS.128 chunks cA/cB, conflict-free per 8-lane phase), guarded by the
// per-plane named barrier. Frame = R11: 512 thr = 2 independent 256-thread
// domains, 2 volumes/CTA, 96 CTAs = one perfect wave.

#define PLANE4 256     // float4 per 32x32 plane
#define RING   5

__device__ __forceinline__ void cpa16(unsigned int s, const void* g) {
    asm volatile("cp.async.cg.shared.global [%0], [%1], 16;" :: "r"(s), "l"(g));
}

__global__ __launch_bounds__(512, 1)
void gru3d_kernel(const float4* __restrict__ zv,
                  const float4* __restrict__ hv,
                  const float*  __restrict__ h0p,
                  float4*       __restrict__ ov)
{
    __shared__ __align__(16) float4 rz[2][RING][PLANE4];   // 40KB
    __shared__ __align__(16) float4 rh[2][RING][PLANE4];   // 40KB
    __shared__ __align__(16) float4 stg[2][2][PLANE4];     // 16KB prev staging

    const float h0 = __ldg(h0p);
    const int tid = threadIdx.x;
    const int dom = tid >> 8;          // 0/1: which volume
    const int t   = tid & 255;
    const int y   = t >> 3;            // 0..31
    const int x4  = t & 7;             // 0..7

    const int vol = blockIdx.x * 2 + dom;
    const size_t base = (size_t)vol * (32 * PLANE4) + (size_t)t;
    const float4* zp = zv + base;
    const float4* hp = hv + base;
    float4*       op = ov + base;

    const unsigned int rz_a =
        (unsigned int)__cvta_generic_to_shared(&rz[dom][0][t]);
    const unsigned int rh_a =
        (unsigned int)__cvta_generic_to_shared(&rh[dom][0][t]);
    const unsigned int SS = PLANE4 * sizeof(float4);   // slot stride (bytes)

    // Prologue: planes 0..3 into ring slots 0..3, one commit group each.
    #pragma unroll
    for (int s = 0; s < 4; ++s) {
        cpa16(rz_a + s * SS, zp + (size_t)s * PLANE4);
        cpa16(rh_a + s * SS, hp + (size_t)s * PLANE4);
        asm volatile("cp.async.commit_group;" ::: "memory");
    }

    // Prev-plane staging read chunks (conflict-free per 8-lane phase).
    const int cB = ((y > 0) ? (y - 1) : 0) * 8 + x4;
    const int cA = (cB > 0) ? (cB - 1) : 0;
    const int bid = 1 + dom;           // named barrier per domain

    #pragma unroll
    for (int d = 0; d < 32; ++d) {
        // Refill plane d+4 into slot (d+4)%RING (my own element; consumed by
        // me at iteration d+4 -> no cross-thread hazard, no barrier needed).
        if (d + 4 < 32) {
            const int sl = (d + 4) % RING;
            cpa16(rz_a + sl * SS, zp + (size_t)(d + 4) * PLANE4);
            cpa16(rh_a + sl * SS, hp + (size_t)(d + 4) * PLANE4);
        }
        // Commit every iteration (empty tail groups keep accounting uniform).
        asm volatile("cp.async.commit_group;" ::: "memory");
        // <=4 groups pending -> the group carrying plane d is complete.
        asm volatile("cp.async.wait_group 4;" ::: "memory");

        const float4 zd = rz[dom][d % RING][t];   // LDS.128, conflict-free
        const float4 hd = rh[dom][d % RING][t];

        // prev = out[d-1] shifted (+1,+1), from staging phase (d+1)&1
        // (written at iteration d-1; visible via that iteration's barrier).
        const float4* pv = &stg[dom][(d + 1) & 1][0];
        const float4 A = pv[cA];
        const float4 B = pv[cB];

        float p0 = A.w, p1 = B.x, p2 = B.y, p3 = B.z;
        if (x4 == 0) p0 = h0;                        // x-1 < 0 border
        if (y == 0 || d == 0) { p0 = h0; p1 = h0; p2 = h0; p3 = h0; }

        float4 o;
        o.x = fmaf(zd.x, hd.x - p0, p0);
        o.y = fmaf(zd.y, hd.y - p1, p1);
        o.z = fmaf(zd.z, hd.z - p2, p2);
        o.w = fmaf(zd.w, hd.w - p3, p3);

        stg[dom][d & 1][t] = o;                      // STS.128, conflict-free
        op[(size_t)d * PLANE4] = o;                  // STG.128

        // Domain-local barrier: staging writes of plane d visible before
        // plane d+1 reads them (phases alternate -> no same-slot race).
        asm volatile("bar.sync %0, 256;" :: "r"(bid) : "memory");
    }
}

extern "C" void kernel_launch(void* const* d_in, const int* in_sizes, int n_in,
                              void* d_out, int out_size)
{
    const float4* z  = (const float4*)d_in[0];
    const float4* ht = (const float4*)d_in[1];
    const float*  h0 = (const float*)d_in[2];
    float4* out = (float4*)d_out;

    const int n_volumes = out_size / (32 * PLANE4 * 4);   // B*C = 192
    gru3d_kernel<<<n_volumes / 2, 512>>>(z, ht, h0, out);
}

// round 17
// speedup vs baseline: 1.1575x; 1.1575x over previous
#include <cuda_runtime.h>
#include <cuda_bf16.h>
#include <cstdint>

// GruDirection3d forward wavefront:
//   out[d,y,x] = z*h_tilde + (1-z)*out[d-1,y-1,x-1],  border -> h0
//
// R17: diagonal-chain kernel, float4, zero-sync. Shift u = y - d: chain
// (vol,u) visits (d, u+d) for d in [d0, d0+n), n = 32-|u|; the dependency
// (d-1,y-1,x-1) is the SAME chain's previous step at x-1. Thread owns a
// float4 of x; warp = 8 x-groups x 4 VOLUMES with the SAME u -> uniform n
// per warp, no divergence. x-shift: p0 = shfl_up(o.w,1,width=8) (group
// boundary -> h0), p1..p3 = own o.x/y/z. i==0 handled by initializing o to
// h0 (the shift then yields h0 everywhere). No smem, no barriers; every
// 128B line read/written exactly once; depth-4 clamped register pipeline
// (uniform addresses -> ptxas batches the LDGs, proven in R4). Longest
// chains (small |u|) get the lowest warp ids -> launched first.

#define S4 264     // float4 stride per chain step: 1056 floats

__global__ __launch_bounds__(256)
void gru3d_diag(const float4* __restrict__ zv,
                const float4* __restrict__ hv,
                const float*  __restrict__ h0p,
                float4*       __restrict__ ov)
{
    const float h0 = __ldg(h0p);
    const int wid  = blockIdx.x * 8 + (threadIdx.x >> 5);
    const int lane = threadIdx.x & 31;
    const int xl   = lane & 7;          // x-group 0..7
    const int vsub = lane >> 3;         // volume sub-index 0..3

    // u ordering by descending chain length: 0,-1,1,-2,2,...
    const int u_idx = wid / 48;         // 0..62
    const int vg    = wid - u_idx * 48; // volume group 0..47
    const int u  = (u_idx & 1) ? -((u_idx + 1) >> 1) : ((u_idx + 1) >> 1);
    const int au = (u < 0) ? -u : u;
    const int n  = 32 - au;             // active steps (uniform per warp)
    const int n4 = (n + 3) & ~3;
    const int d0 = (u < 0) ? -u : 0;
    const int y0 = (u > 0) ?  u : 0;

    const int vol = vg * 4 + vsub;
    const size_t b4 = (size_t)vol * 8192 + (size_t)d0 * 256 + y0 * 8 + xl;
    const float4* zp = zv + b4;
    const float4* hp = hv + b4;
    float4*       op = ov + b4;

    // Depth-4 register pipeline (clamped to last valid step: L1 re-hits).
    float4 zb[4], hb[4];
    #pragma unroll
    for (int k = 0; k < 4; ++k) {
        const int t = (k < n) ? k : (n - 1);
        zb[k] = zp[(size_t)t * S4];
        hb[k] = hp[(size_t)t * S4];
    }

    float4 o = make_float4(h0, h0, h0, h0);   // step-0 prev == h0 border

    for (int i = 0; i < n4; i += 4) {
        #pragma unroll
        for (int k = 0; k < 4; ++k) {
            const float4 zc = zb[k];
            const float4 hc = hb[k];

            // Refill stage k with step i+k+4 (clamped, uniform).
            int t = i + k + 4;
            if (t > n - 1) t = n - 1;
            zb[k] = zp[(size_t)t * S4];
            hb[k] = hp[(size_t)t * S4];

            // Shifted prev: x-1 within the 8-lane volume segment.
            const float pw = __shfl_up_sync(0xffffffffu, o.w, 1, 8);
            const float p0 = (xl == 0) ? h0 : pw;

            float4 no;
            no.x = fmaf(zc.x, hc.x - p0,  p0);
            no.y = fmaf(zc.y, hc.y - o.x, o.x);
            no.z = fmaf(zc.z, hc.z - o.y, o.y);
            no.w = fmaf(zc.w, hc.w - o.z, o.z);

            if (i + k < n) op[(size_t)(i + k) * S4] = no;
            o = no;
        }
    }
}

extern "C" void kernel_launch(void* const* d_in, const int* in_sizes, int n_in,
                              void* d_out, int out_size)
{
    const float4* z  = (const float4*)d_in[0];
    const float4* ht = (const float4*)d_in[1];
    const float*  h0 = (const float*)d_in[2];
    float4* out = (float4*)d_out;

    // 63 u-values x 48 volume-groups = 3024 warps = 378 CTAs x 8 warps.
    gru3d_diag<<<378, 256>>>(z, ht, h0, out);
}